// round 3
// baseline (speedup 1.0000x reference)
#include <cuda_runtime.h>

#define NTN 500000
#define NCN 100000
#define NMN 20000
#define EN  500000

// ---------------- device scratch (no dynamic allocation allowed) ----------------
__device__ __align__(256) float g_aggC[(size_t)NCN * 128];   // 51.2 MB  sum of features per client
__device__ __align__(256) float g_aggM[(size_t)NMN * 128];   // 10.2 MB  sum of features per merchant
__device__ int   g_cntC[NCN];
__device__ int   g_cntM[NMN];
__device__ int   g_cntT1[NTN];          // in-degree of transactions via c2t
__device__ int   g_cntT2[NTN];          // in-degree of transactions via m2t
__device__ float g_invT1[NTN];
__device__ float g_invT2[NTN];
__device__ __align__(256) float g_pC[(size_t)NCN * 2];       // projected per-client message (2 floats)
__device__ __align__(256) float g_pM[(size_t)NMN * 2];
__device__ __align__(16)  float g_qC[128];                   // W1_c2t @ Wf   (64x2)
__device__ __align__(16)  float g_qM[128];                   // W1_m2t @ Wf
__device__ __align__(16)  float g_rbC[2];                    // b1_c2t @ Wf
__device__ __align__(16)  float g_rbM[2];                    // b1_m2t @ Wf

// ---------------- vector reductions (sm_90+: red.global.add.vN.f32) ----------------
__device__ __forceinline__ void red_add_v4(float* addr, float x, float y, float z, float w) {
    asm volatile("red.global.add.v4.f32 [%0], {%1, %2, %3, %4};"
                 :: "l"(addr), "f"(x), "f"(y), "f"(z), "f"(w) : "memory");
}
__device__ __forceinline__ void red_add_v2(float* addr, float x, float y) {
    asm volatile("red.global.add.v2.f32 [%0], {%1, %2};"
                 :: "l"(addr), "f"(x), "f"(y) : "memory");
}

// ---------------- kernels ----------------

// histogram of dst indices for all 4 needed relations
__global__ void count_kernel(const int* __restrict__ d_c2t, const int* __restrict__ d_m2t,
                             const int* __restrict__ d_t2c, const int* __restrict__ d_t2m)
{
    int i = blockIdx.x * blockDim.x + threadIdx.x;
    if (i < EN)            atomicAdd(&g_cntT1[d_c2t[i]], 1);
    else if (i < 2 * EN)   atomicAdd(&g_cntT2[d_m2t[i - EN]], 1);
    else if (i < 3 * EN)   atomicAdd(&g_cntC[d_t2c[i - 2 * EN]], 1);
    else if (i < 4 * EN)   atomicAdd(&g_cntM[d_t2m[i - 3 * EN]], 1);
}

__global__ void inv_kernel()
{
    int i = blockIdx.x * blockDim.x + threadIdx.x;
    if (i < NTN) {
        int c1 = g_cntT1[i]; g_invT1[i] = 1.0f / (float)(c1 > 0 ? c1 : 1);
        int c2 = g_cntT2[i]; g_invT2[i] = 1.0f / (float)(c2 > 0 ? c2 : 1);
    }
}

// q = W1 @ Wf (64x64 @ 64x2), rb = b1 @ Wf   — tiny, one block
__global__ void precompute_q_kernel(const float* __restrict__ W1c, const float* __restrict__ b1c,
                                    const float* __restrict__ W1m, const float* __restrict__ b1m,
                                    const float* __restrict__ Wf)
{
    int tid = threadIdx.x;  // 256 threads
    if (tid < 128) {
        int k = tid >> 1, j = tid & 1;
        float s = 0.f;
        #pragma unroll
        for (int h = 0; h < 64; h++) s = fmaf(W1c[k * 64 + h], Wf[h * 2 + j], s);
        g_qC[tid] = s;
    } else {
        int t = tid - 128;
        int k = t >> 1, j = t & 1;
        float s = 0.f;
        #pragma unroll
        for (int h = 0; h < 64; h++) s = fmaf(W1m[k * 64 + h], Wf[h * 2 + j], s);
        g_qM[t] = s;
    }
    if (tid < 2) {
        float s = 0.f;
        #pragma unroll
        for (int h = 0; h < 64; h++) s = fmaf(b1c[h], Wf[h * 2 + tid], s);
        g_rbC[tid] = s;
    }
    if (tid >= 128 && tid < 130) {
        int j = tid - 128;
        float s = 0.f;
        #pragma unroll
        for (int h = 0; h < 64; h++) s = fmaf(b1m[h], Wf[h * 2 + j], s);
        g_rbM[j] = s;
    }
}

// out[t] starts at bf (zero-in-degree transactions output exactly bf)
__global__ void out_init_kernel(const float* __restrict__ bf, float* __restrict__ out)
{
    int i = blockIdx.x * blockDim.x + threadIdx.x;
    if (i < NTN) {
        float2 v = make_float2(bf[0], bf[1]);
        ((float2*)out)[i] = v;
    }
}

// layer-0 aggregation: one warp per edge, 32 lanes x float4 = full 128-float feature row
__global__ __launch_bounds__(256) void scatter0_kernel(
    const float* __restrict__ feat,
    const int* __restrict__ s_t2c, const int* __restrict__ d_t2c,
    const int* __restrict__ s_t2m, const int* __restrict__ d_t2m)
{
    long long gt = (long long)blockIdx.x * blockDim.x + threadIdx.x;
    int w = (int)(gt >> 5);
    int lane = (int)(gt & 31);
    if (w >= 2 * EN) return;
    int s, d;
    float* dst;
    if (w < EN) {
        s = s_t2c[w]; d = d_t2c[w];
        dst = g_aggC + (size_t)d * 128;
    } else {
        int e = w - EN;
        s = s_t2m[e]; d = d_t2m[e];
        dst = g_aggM + (size_t)d * 128;
    }
    float4 v = *(const float4*)(feat + (size_t)s * 128 + lane * 4);
    red_add_v4(dst + lane * 4, v.x, v.y, v.z, v.w);
}

// fused: h0 = lrelu(mean_agg @ W0 + b0*(cnt>0));  p = h0 @ q + rb   (rows x 2 output)
// block computes a 64-row x 64-col hidden tile, then half-warp-reduces the 2-d projection.
__global__ __launch_bounds__(256) void gemm_layer0_kernel(
    const float* __restrict__ A, const int* __restrict__ cnt,
    const float* __restrict__ W0, const float* __restrict__ b0,
    const float* __restrict__ q, const float* __restrict__ rb,
    float* __restrict__ p_out, int M)
{
    __shared__ float sA[64 * 64];
    __shared__ float sW[64 * 64];
    __shared__ float sb[64];
    __shared__ float sq[128];
    __shared__ float srb[2];

    const int tid = threadIdx.x;
    const int row0 = blockIdx.x * 64;
    if (tid < 64) sb[tid] = b0[tid];
    if (tid >= 64 && tid < 192) sq[tid - 64] = q[tid - 64];
    if (tid >= 192 && tid < 194) srb[tid - 192] = rb[tid - 192];

    float acc[4][4];
    #pragma unroll
    for (int i = 0; i < 4; i++)
        #pragma unroll
        for (int j = 0; j < 4; j++) acc[i][j] = 0.f;

    const int tx = tid & 15;   // col group (4 cols each)
    const int ty = tid >> 4;   // row group (4 rows each)

    for (int k0 = 0; k0 < 128; k0 += 64) {
        #pragma unroll
        for (int l = 0; l < 16; l++) {
            int idx = l * 256 + tid;
            int r = idx >> 6, kk = idx & 63;
            int gr = row0 + r;
            sA[idx] = (gr < M) ? A[(size_t)gr * 128 + k0 + kk] : 0.f;
        }
        #pragma unroll
        for (int l = 0; l < 16; l++) {
            int idx = l * 256 + tid;
            int kk = idx >> 6, c = idx & 63;
            sW[idx] = W0[(size_t)(k0 + kk) * 64 + c];
        }
        __syncthreads();
        #pragma unroll
        for (int kk = 0; kk < 64; kk++) {
            float a[4], b[4];
            #pragma unroll
            for (int i = 0; i < 4; i++) a[i] = sA[(ty * 4 + i) * 64 + kk];
            #pragma unroll
            for (int j = 0; j < 4; j++) b[j] = sW[kk * 64 + tx * 4 + j];
            #pragma unroll
            for (int i = 0; i < 4; i++)
                #pragma unroll
                for (int j = 0; j < 4; j++)
                    acc[i][j] = fmaf(a[i], b[j], acc[i][j]);
        }
        __syncthreads();
    }

    // epilogue: mean-normalize, bias-gate, leaky_relu, project to 2 dims, reduce over tx
    #pragma unroll
    for (int i = 0; i < 4; i++) {
        int r = row0 + ty * 4 + i;     // uniform across each half-warp
        float p0 = 0.f, p1 = 0.f;
        if (r < M) {
            int c = cnt[r];
            float invr = 1.0f / (float)(c > 0 ? c : 1);
            float gate = (c > 0) ? 1.0f : 0.0f;
            #pragma unroll
            for (int j = 0; j < 4; j++) {
                int col = tx * 4 + j;
                float v = acc[i][j] * invr + sb[col] * gate;
                v = (v > 0.f) ? v : 0.01f * v;      // leaky_relu, slope 0.01
                p0 = fmaf(v, sq[col * 2],     p0);
                p1 = fmaf(v, sq[col * 2 + 1], p1);
            }
        }
        // reduce across the 16 tx lanes of each half-warp (xor offsets stay within halves)
        #pragma unroll
        for (int o = 8; o >= 1; o >>= 1) {
            p0 += __shfl_xor_sync(0xffffffffu, p0, o);
            p1 += __shfl_xor_sync(0xffffffffu, p1, o);
        }
        if (tx == 0 && r < M) {
            p_out[(size_t)r * 2]     = p0 + srb[0];
            p_out[(size_t)r * 2 + 1] = p1 + srb[1];
        }
    }
}

// layer-1 scatter (post-projection): one thread per edge, 8 bytes of payload
__global__ __launch_bounds__(256) void scatter2_kernel(
    const int* __restrict__ s_c2t, const int* __restrict__ d_c2t,
    const int* __restrict__ s_m2t, const int* __restrict__ d_m2t,
    float* __restrict__ out)
{
    int i = blockIdx.x * blockDim.x + threadIdx.x;
    if (i >= 2 * EN) return;
    int s, d;
    const float* p;
    float inv;
    if (i < EN) {
        s = s_c2t[i]; d = d_c2t[i];
        p = g_pC + (size_t)s * 2;
        inv = g_invT1[d];
    } else {
        int e = i - EN;
        s = s_m2t[e]; d = d_m2t[e];
        p = g_pM + (size_t)s * 2;
        inv = g_invT2[d];
    }
    float2 v = *(const float2*)p;
    red_add_v2(out + (size_t)d * 2, v.x * inv, v.y * inv);
}

// ---------------- launch ----------------
extern "C" void kernel_launch(void* const* d_in, const int* in_sizes, int n_in,
                              void* d_out, int out_size)
{
    (void)in_sizes; (void)n_in; (void)out_size;

    const float* feat   = (const float*)d_in[0];
    const int* s_c2t    = (const int*)d_in[3];
    const int* d_c2t    = (const int*)d_in[4];
    const int* s_m2t    = (const int*)d_in[5];
    const int* d_m2t    = (const int*)d_in[6];
    const int* s_t2c    = (const int*)d_in[7];
    const int* d_t2c    = (const int*)d_in[8];
    const int* s_t2m    = (const int*)d_in[9];
    const int* d_t2m    = (const int*)d_in[10];
    const float* W1_c2t = (const float*)d_in[13];
    const float* b1_c2t = (const float*)d_in[14];
    const float* W1_m2t = (const float*)d_in[17];
    const float* b1_m2t = (const float*)d_in[18];
    const float* W0_t2c = (const float*)d_in[19];
    const float* b0_t2c = (const float*)d_in[20];
    const float* W0_t2m = (const float*)d_in[23];
    const float* b0_t2m = (const float*)d_in[24];
    const float* Wf     = (const float*)d_in[27];
    const float* bf     = (const float*)d_in[28];
    float* out = (float*)d_out;

    void *aggC_p, *aggM_p, *cntC_p, *cntM_p, *cntT1_p, *cntT2_p;
    void *pC_p, *pM_p, *qC_p, *qM_p, *rbC_p, *rbM_p;
    cudaGetSymbolAddress(&aggC_p,  g_aggC);
    cudaGetSymbolAddress(&aggM_p,  g_aggM);
    cudaGetSymbolAddress(&cntC_p,  g_cntC);
    cudaGetSymbolAddress(&cntM_p,  g_cntM);
    cudaGetSymbolAddress(&cntT1_p, g_cntT1);
    cudaGetSymbolAddress(&cntT2_p, g_cntT2);
    cudaGetSymbolAddress(&pC_p,    g_pC);
    cudaGetSymbolAddress(&pM_p,    g_pM);
    cudaGetSymbolAddress(&qC_p,    g_qC);
    cudaGetSymbolAddress(&qM_p,    g_qM);
    cudaGetSymbolAddress(&rbC_p,   g_rbC);
    cudaGetSymbolAddress(&rbM_p,   g_rbM);

    cudaMemsetAsync(aggC_p,  0, sizeof(g_aggC),  0);
    cudaMemsetAsync(aggM_p,  0, sizeof(g_aggM),  0);
    cudaMemsetAsync(cntC_p,  0, sizeof(g_cntC),  0);
    cudaMemsetAsync(cntM_p,  0, sizeof(g_cntM),  0);
    cudaMemsetAsync(cntT1_p, 0, sizeof(g_cntT1), 0);
    cudaMemsetAsync(cntT2_p, 0, sizeof(g_cntT2), 0);

    count_kernel<<<(4 * EN + 255) / 256, 256>>>(d_c2t, d_m2t, d_t2c, d_t2m);
    inv_kernel<<<(NTN + 255) / 256, 256>>>();
    precompute_q_kernel<<<1, 256>>>(W1_c2t, b1_c2t, W1_m2t, b1_m2t, Wf);
    out_init_kernel<<<(NTN + 255) / 256, 256>>>(bf, out);

    {
        long long threads = (long long)2 * EN * 32;
        int blocks = (int)((threads + 255) / 256);
        scatter0_kernel<<<blocks, 256>>>(feat, s_t2c, d_t2c, s_t2m, d_t2m);
    }

    gemm_layer0_kernel<<<(NCN + 63) / 64, 256>>>(
        (const float*)aggC_p, (const int*)cntC_p, W0_t2c, b0_t2c,
        (const float*)qC_p, (const float*)rbC_p, (float*)pC_p, NCN);
    gemm_layer0_kernel<<<(NMN + 63) / 64, 256>>>(
        (const float*)aggM_p, (const int*)cntM_p, W0_t2m, b0_t2m,
        (const float*)qM_p, (const float*)rbM_p, (float*)pM_p, NMN);

    scatter2_kernel<<<(2 * EN + 255) / 256, 256>>>(s_c2t, d_c2t, s_m2t, d_m2t, out);
}

// round 7
// speedup vs baseline: 1.2085x; 1.2085x over previous
#include <cuda_runtime.h>

#define NTN 500000
#define NCN 100000
#define NMN 20000
#define EN  500000

#define NB_C ((NCN + 255) / 256)   // 391
#define NB_M ((NMN + 255) / 256)   // 79

// ---------------- device scratch (no dynamic allocation allowed) ----------------
__device__ __align__(256) float g_aggC[(size_t)NCN * 128];   // 51.2 MB  sum of features per client
__device__ __align__(256) float g_aggM[(size_t)NMN * 128];   // 10.2 MB  sum of features per merchant
__device__ int   g_cntC[NCN];
__device__ int   g_cntM[NMN];
__device__ int   g_cntT1[NTN];          // in-degree of transactions via c2t
__device__ int   g_cntT2[NTN];          // in-degree of transactions via m2t
__device__ float g_invT1[NTN];
__device__ float g_invT2[NTN];
__device__ int   g_baseC[NCN];          // CSR row starts (exclusive scan of cntC)
__device__ int   g_baseM[NMN];
__device__ int   g_curC[NCN];           // bucket fill cursors (mutable copy of base)
__device__ int   g_curM[NMN];
__device__ int   g_permC[EN];           // src indices sorted by dst
__device__ int   g_permM[EN];
__device__ int   g_bsum[512];
__device__ int   g_bbase[512];
__device__ __align__(256) float g_pC[(size_t)NCN * 2];       // projected per-client message (2 floats)
__device__ __align__(256) float g_pM[(size_t)NMN * 2];
__device__ __align__(16)  float g_qC[128];                   // W1_c2t @ Wf   (64x2)
__device__ __align__(16)  float g_qM[128];                   // W1_m2t @ Wf
__device__ __align__(16)  float g_rbC[2];                    // b1_c2t @ Wf
__device__ __align__(16)  float g_rbM[2];                    // b1_m2t @ Wf

__device__ __forceinline__ void red_add_v2(float* addr, float x, float y) {
    asm volatile("red.global.add.v2.f32 [%0], {%1, %2};"
                 :: "l"(addr), "f"(x), "f"(y) : "memory");
}

// ---------------- kernels ----------------

// histogram of dst indices for all 4 needed relations
__global__ void count_kernel(const int* __restrict__ d_c2t, const int* __restrict__ d_m2t,
                             const int* __restrict__ d_t2c, const int* __restrict__ d_t2m)
{
    int i = blockIdx.x * blockDim.x + threadIdx.x;
    if (i < EN)            atomicAdd(&g_cntT1[d_c2t[i]], 1);
    else if (i < 2 * EN)   atomicAdd(&g_cntT2[d_m2t[i - EN]], 1);
    else if (i < 3 * EN)   atomicAdd(&g_cntC[d_t2c[i - 2 * EN]], 1);
    else if (i < 4 * EN)   atomicAdd(&g_cntM[d_t2m[i - 3 * EN]], 1);
}

__global__ void inv_kernel()
{
    int i = blockIdx.x * blockDim.x + threadIdx.x;
    if (i < NTN) {
        int c1 = g_cntT1[i]; g_invT1[i] = 1.0f / (float)(c1 > 0 ? c1 : 1);
        int c2 = g_cntT2[i]; g_invT2[i] = 1.0f / (float)(c2 > 0 ? c2 : 1);
    }
}

// ---- two-level exclusive prefix scan of cnt -> base (+ mutable cursor copy) ----
__global__ void blocksum_kernel(const int* __restrict__ cnt, int n, int* __restrict__ bsum)
{
    __shared__ int s[256];
    int i = blockIdx.x * 256 + threadIdx.x;
    s[threadIdx.x] = (i < n) ? cnt[i] : 0;
    __syncthreads();
    #pragma unroll
    for (int o = 128; o > 0; o >>= 1) {
        if (threadIdx.x < o) s[threadIdx.x] += s[threadIdx.x + o];
        __syncthreads();
    }
    if (threadIdx.x == 0) bsum[blockIdx.x] = s[0];
}

__global__ void scan_bsum_kernel(const int* __restrict__ bsum, int nb, int* __restrict__ bbase)
{
    __shared__ int s[512];
    int t = threadIdx.x;
    int v = (t < nb) ? bsum[t] : 0;
    s[t] = v;
    __syncthreads();
    #pragma unroll
    for (int o = 1; o < 512; o <<= 1) {
        int add = (t >= o) ? s[t - o] : 0;
        __syncthreads();
        s[t] += add;
        __syncthreads();
    }
    if (t < nb) bbase[t] = s[t] - v;   // exclusive
}

__global__ void finalize_base_kernel(const int* __restrict__ cnt, int n,
                                     const int* __restrict__ bbase,
                                     int* __restrict__ base, int* __restrict__ cur)
{
    __shared__ int s[256];
    int t = threadIdx.x;
    int i = blockIdx.x * 256 + t;
    int v = (i < n) ? cnt[i] : 0;
    s[t] = v;
    __syncthreads();
    #pragma unroll
    for (int o = 1; o < 256; o <<= 1) {
        int add = (t >= o) ? s[t - o] : 0;
        __syncthreads();
        s[t] += add;
        __syncthreads();
    }
    if (i < n) {
        int b = bbase[blockIdx.x] + s[t] - v;
        base[i] = b;
        cur[i]  = b;
    }
}

// counting-sort edges by destination: perm holds src indices grouped by dst
__global__ void bucket_kernel(const int* __restrict__ src, const int* __restrict__ dst,
                              int* __restrict__ cur, int* __restrict__ perm)
{
    int i = blockIdx.x * blockDim.x + threadIdx.x;
    if (i < EN) {
        int d = dst[i];
        int pos = atomicAdd(&cur[d], 1);
        perm[pos] = src[i];
    }
}

// q = W1 @ Wf (64x64 @ 64x2), rb = b1 @ Wf   — tiny, one block
__global__ void precompute_q_kernel(const float* __restrict__ W1c, const float* __restrict__ b1c,
                                    const float* __restrict__ W1m, const float* __restrict__ b1m,
                                    const float* __restrict__ Wf)
{
    int tid = threadIdx.x;  // 256 threads
    if (tid < 128) {
        int k = tid >> 1, j = tid & 1;
        float s = 0.f;
        #pragma unroll
        for (int h = 0; h < 64; h++) s = fmaf(W1c[k * 64 + h], Wf[h * 2 + j], s);
        g_qC[tid] = s;
    } else {
        int t = tid - 128;
        int k = t >> 1, j = t & 1;
        float s = 0.f;
        #pragma unroll
        for (int h = 0; h < 64; h++) s = fmaf(W1m[k * 64 + h], Wf[h * 2 + j], s);
        g_qM[t] = s;
    }
    if (tid < 2) {
        float s = 0.f;
        #pragma unroll
        for (int h = 0; h < 64; h++) s = fmaf(b1c[h], Wf[h * 2 + tid], s);
        g_rbC[tid] = s;
    }
    if (tid >= 128 && tid < 130) {
        int j = tid - 128;
        float s = 0.f;
        #pragma unroll
        for (int h = 0; h < 64; h++) s = fmaf(b1m[h], Wf[h * 2 + j], s);
        g_rbM[j] = s;
    }
}

// out[t] starts at bf (zero-in-degree transactions output exactly bf)
__global__ void out_init_kernel(const float* __restrict__ bf, float* __restrict__ out)
{
    int i = blockIdx.x * blockDim.x + threadIdx.x;
    if (i < NTN) {
        float2 v = make_float2(bf[0], bf[1]);
        ((float2*)out)[i] = v;
    }
}

// layer-0 aggregation as GATHER: one warp per dst node, register accumulation,
// single plain store — no global reductions at all.
__global__ __launch_bounds__(256) void gather_kernel(
    const float* __restrict__ feat,
    const int* __restrict__ perm, const int* __restrict__ base,
    const int* __restrict__ cnt, float* __restrict__ agg, int n)
{
    int w = (int)((blockIdx.x * (long long)blockDim.x + threadIdx.x) >> 5);
    int lane = threadIdx.x & 31;
    if (w >= n) return;
    int b = base[w];
    int c = cnt[w];
    float4 a0 = make_float4(0.f, 0.f, 0.f, 0.f);
    float4 a1 = make_float4(0.f, 0.f, 0.f, 0.f);
    int e = 0;
    for (; e + 1 < c; e += 2) {
        int s0 = __ldg(&perm[b + e]);
        int s1 = __ldg(&perm[b + e + 1]);
        float4 v0 = *(const float4*)(feat + (size_t)s0 * 128 + lane * 4);
        float4 v1 = *(const float4*)(feat + (size_t)s1 * 128 + lane * 4);
        a0.x += v0.x; a0.y += v0.y; a0.z += v0.z; a0.w += v0.w;
        a1.x += v1.x; a1.y += v1.y; a1.z += v1.z; a1.w += v1.w;
    }
    if (e < c) {
        int s0 = __ldg(&perm[b + e]);
        float4 v0 = *(const float4*)(feat + (size_t)s0 * 128 + lane * 4);
        a0.x += v0.x; a0.y += v0.y; a0.z += v0.z; a0.w += v0.w;
    }
    a0.x += a1.x; a0.y += a1.y; a0.z += a1.z; a0.w += a1.w;
    *(float4*)(agg + (size_t)w * 128 + lane * 4) = a0;
}

// fused: h0 = lrelu(mean_agg @ W0 + b0*(cnt>0));  p = h0 @ q + rb   (rows x 2 output)
__global__ __launch_bounds__(256) void gemm_layer0_kernel(
    const float* __restrict__ A, const int* __restrict__ cnt,
    const float* __restrict__ W0, const float* __restrict__ b0,
    const float* __restrict__ q, const float* __restrict__ rb,
    float* __restrict__ p_out, int M)
{
    __shared__ float sA[64 * 64];
    __shared__ float sW[64 * 64];
    __shared__ float sb[64];
    __shared__ float sq[128];
    __shared__ float srb[2];

    const int tid = threadIdx.x;
    const int row0 = blockIdx.x * 64;
    if (tid < 64) sb[tid] = b0[tid];
    if (tid >= 64 && tid < 192) sq[tid - 64] = q[tid - 64];
    if (tid >= 192 && tid < 194) srb[tid - 192] = rb[tid - 192];

    float acc[4][4];
    #pragma unroll
    for (int i = 0; i < 4; i++)
        #pragma unroll
        for (int j = 0; j < 4; j++) acc[i][j] = 0.f;

    const int tx = tid & 15;   // col group (4 cols each)
    const int ty = tid >> 4;   // row group (4 rows each)

    for (int k0 = 0; k0 < 128; k0 += 64) {
        #pragma unroll
        for (int l = 0; l < 16; l++) {
            int idx = l * 256 + tid;
            int r = idx >> 6, kk = idx & 63;
            int gr = row0 + r;
            sA[idx] = (gr < M) ? A[(size_t)gr * 128 + k0 + kk] : 0.f;
        }
        #pragma unroll
        for (int l = 0; l < 16; l++) {
            int idx = l * 256 + tid;
            int kk = idx >> 6, c = idx & 63;
            sW[idx] = W0[(size_t)(k0 + kk) * 64 + c];
        }
        __syncthreads();
        #pragma unroll
        for (int kk = 0; kk < 64; kk++) {
            float a[4], b[4];
            #pragma unroll
            for (int i = 0; i < 4; i++) a[i] = sA[(ty * 4 + i) * 64 + kk];
            #pragma unroll
            for (int j = 0; j < 4; j++) b[j] = sW[kk * 64 + tx * 4 + j];
            #pragma unroll
            for (int i = 0; i < 4; i++)
                #pragma unroll
                for (int j = 0; j < 4; j++)
                    acc[i][j] = fmaf(a[i], b[j], acc[i][j]);
        }
        __syncthreads();
    }

    // epilogue: mean-normalize, bias-gate, leaky_relu, project to 2 dims, reduce over tx
    #pragma unroll
    for (int i = 0; i < 4; i++) {
        int r = row0 + ty * 4 + i;
        float p0 = 0.f, p1 = 0.f;
        if (r < M) {
            int c = cnt[r];
            float invr = 1.0f / (float)(c > 0 ? c : 1);
            float gate = (c > 0) ? 1.0f : 0.0f;
            #pragma unroll
            for (int j = 0; j < 4; j++) {
                int col = tx * 4 + j;
                float v = acc[i][j] * invr + sb[col] * gate;
                v = (v > 0.f) ? v : 0.01f * v;      // leaky_relu, slope 0.01
                p0 = fmaf(v, sq[col * 2],     p0);
                p1 = fmaf(v, sq[col * 2 + 1], p1);
            }
        }
        #pragma unroll
        for (int o = 8; o >= 1; o >>= 1) {
            p0 += __shfl_xor_sync(0xffffffffu, p0, o);
            p1 += __shfl_xor_sync(0xffffffffu, p1, o);
        }
        if (tx == 0 && r < M) {
            p_out[(size_t)r * 2]     = p0 + srb[0];
            p_out[(size_t)r * 2 + 1] = p1 + srb[1];
        }
    }
}

// layer-1 scatter (post-projection): one thread per edge, 8 bytes of payload
__global__ __launch_bounds__(256) void scatter2_kernel(
    const int* __restrict__ s_c2t, const int* __restrict__ d_c2t,
    const int* __restrict__ s_m2t, const int* __restrict__ d_m2t,
    float* __restrict__ out)
{
    int i = blockIdx.x * blockDim.x + threadIdx.x;
    if (i >= 2 * EN) return;
    int s, d;
    const float* p;
    float inv;
    if (i < EN) {
        s = s_c2t[i]; d = d_c2t[i];
        p = g_pC + (size_t)s * 2;
        inv = g_invT1[d];
    } else {
        int e = i - EN;
        s = s_m2t[e]; d = d_m2t[e];
        p = g_pM + (size_t)s * 2;
        inv = g_invT2[d];
    }
    float2 v = *(const float2*)p;
    red_add_v2(out + (size_t)d * 2, v.x * inv, v.y * inv);
}

// ---------------- launch ----------------
extern "C" void kernel_launch(void* const* d_in, const int* in_sizes, int n_in,
                              void* d_out, int out_size)
{
    (void)in_sizes; (void)n_in; (void)out_size;

    const float* feat   = (const float*)d_in[0];
    const int* s_c2t    = (const int*)d_in[3];
    const int* d_c2t    = (const int*)d_in[4];
    const int* s_m2t    = (const int*)d_in[5];
    const int* d_m2t    = (const int*)d_in[6];
    const int* s_t2c    = (const int*)d_in[7];
    const int* d_t2c    = (const int*)d_in[8];
    const int* s_t2m    = (const int*)d_in[9];
    const int* d_t2m    = (const int*)d_in[10];
    const float* W1_c2t = (const float*)d_in[13];
    const float* b1_c2t = (const float*)d_in[14];
    const float* W1_m2t = (const float*)d_in[17];
    const float* b1_m2t = (const float*)d_in[18];
    const float* W0_t2c = (const float*)d_in[19];
    const float* b0_t2c = (const float*)d_in[20];
    const float* W0_t2m = (const float*)d_in[23];
    const float* b0_t2m = (const float*)d_in[24];
    const float* Wf     = (const float*)d_in[27];
    const float* bf     = (const float*)d_in[28];
    float* out = (float*)d_out;

    void *aggC_p, *aggM_p, *cntC_p, *cntM_p, *cntT1_p, *cntT2_p;
    void *baseC_p, *baseM_p, *curC_p, *curM_p, *permC_p, *permM_p;
    void *bsum_p, *bbase_p;
    void *pC_p, *pM_p, *qC_p, *qM_p, *rbC_p, *rbM_p;
    cudaGetSymbolAddress(&aggC_p,  g_aggC);
    cudaGetSymbolAddress(&aggM_p,  g_aggM);
    cudaGetSymbolAddress(&cntC_p,  g_cntC);
    cudaGetSymbolAddress(&cntM_p,  g_cntM);
    cudaGetSymbolAddress(&cntT1_p, g_cntT1);
    cudaGetSymbolAddress(&cntT2_p, g_cntT2);
    cudaGetSymbolAddress(&baseC_p, g_baseC);
    cudaGetSymbolAddress(&baseM_p, g_baseM);
    cudaGetSymbolAddress(&curC_p,  g_curC);
    cudaGetSymbolAddress(&curM_p,  g_curM);
    cudaGetSymbolAddress(&permC_p, g_permC);
    cudaGetSymbolAddress(&permM_p, g_permM);
    cudaGetSymbolAddress(&bsum_p,  g_bsum);
    cudaGetSymbolAddress(&bbase_p, g_bbase);
    cudaGetSymbolAddress(&pC_p,    g_pC);
    cudaGetSymbolAddress(&pM_p,    g_pM);
    cudaGetSymbolAddress(&qC_p,    g_qC);
    cudaGetSymbolAddress(&qM_p,    g_qM);
    cudaGetSymbolAddress(&rbC_p,   g_rbC);
    cudaGetSymbolAddress(&rbM_p,   g_rbM);

    cudaMemsetAsync(cntC_p,  0, sizeof(g_cntC),  0);
    cudaMemsetAsync(cntM_p,  0, sizeof(g_cntM),  0);
    cudaMemsetAsync(cntT1_p, 0, sizeof(g_cntT1), 0);
    cudaMemsetAsync(cntT2_p, 0, sizeof(g_cntT2), 0);

    count_kernel<<<(4 * EN + 255) / 256, 256>>>(d_c2t, d_m2t, d_t2c, d_t2m);
    inv_kernel<<<(NTN + 255) / 256, 256>>>();
    precompute_q_kernel<<<1, 256>>>(W1_c2t, b1_c2t, W1_m2t, b1_m2t, Wf);
    out_init_kernel<<<(NTN + 255) / 256, 256>>>(bf, out);

    // ---- build CSR for t2c (clients) ----
    blocksum_kernel<<<NB_C, 256>>>((const int*)cntC_p, NCN, (int*)bsum_p);
    scan_bsum_kernel<<<1, 512>>>((const int*)bsum_p, NB_C, (int*)bbase_p);
    finalize_base_kernel<<<NB_C, 256>>>((const int*)cntC_p, NCN, (const int*)bbase_p,
                                        (int*)baseC_p, (int*)curC_p);
    bucket_kernel<<<(EN + 255) / 256, 256>>>(s_t2c, d_t2c, (int*)curC_p, (int*)permC_p);

    // ---- build CSR for t2m (merchants) ----
    blocksum_kernel<<<NB_M, 256>>>((const int*)cntM_p, NMN, (int*)bsum_p);
    scan_bsum_kernel<<<1, 512>>>((const int*)bsum_p, NB_M, (int*)bbase_p);
    finalize_base_kernel<<<NB_M, 256>>>((const int*)cntM_p, NMN, (const int*)bbase_p,
                                        (int*)baseM_p, (int*)curM_p);
    bucket_kernel<<<(EN + 255) / 256, 256>>>(s_t2m, d_t2m, (int*)curM_p, (int*)permM_p);

    // ---- layer-0 aggregation via gather (no atomics, no accumulator memset) ----
    gather_kernel<<<(NCN * 32 + 255) / 256, 256>>>(
        feat, (const int*)permC_p, (const int*)baseC_p, (const int*)cntC_p,
        (float*)aggC_p, NCN);
    gather_kernel<<<(NMN * 32 + 255) / 256, 256>>>(
        feat, (const int*)permM_p, (const int*)baseM_p, (const int*)cntM_p,
        (float*)aggM_p, NMN);

    gemm_layer0_kernel<<<(NCN + 63) / 64, 256>>>(
        (const float*)aggC_p, (const int*)cntC_p, W0_t2c, b0_t2c,
        (const float*)qC_p, (const float*)rbC_p, (float*)pC_p, NCN);
    gemm_layer0_kernel<<<(NMN + 63) / 64, 256>>>(
        (const float*)aggM_p, (const int*)cntM_p, W0_t2m, b0_t2m,
        (const float*)qM_p, (const float*)rbM_p, (float*)pM_p, NMN);

    scatter2_kernel<<<(2 * EN + 255) / 256, 256>>>(s_c2t, d_c2t, s_m2t, d_m2t, out);
}

// round 10
// speedup vs baseline: 1.2157x; 1.0060x over previous
#include <cuda_runtime.h>

#define NTN 500000
#define NCN 100000
#define NMN 20000
#define EN  500000

#define NB_C ((NCN + 255) / 256)   // 391
#define NB_M ((NMN + 255) / 256)   // 79
#define NBF_C ((NCN + 63) / 64)    // 1563 fused blocks (clients)
#define NBF_M ((NMN + 63) / 64)    // 313  fused blocks (merchants)

// ---------------- device scratch (no dynamic allocation allowed) ----------------
__device__ int   g_cntC[NCN];
__device__ int   g_cntM[NMN];
__device__ int   g_cntT1[NTN];
__device__ int   g_cntT2[NTN];
__device__ float g_invT1[NTN];
__device__ float g_invT2[NTN];
__device__ int   g_baseC[NCN];
__device__ int   g_baseM[NMN];
__device__ int   g_curC[NCN];
__device__ int   g_curM[NMN];
__device__ int   g_permC[EN];
__device__ int   g_permM[EN];
__device__ int   g_bsumC[512];
__device__ int   g_bbaseC[512];
__device__ int   g_bsumM[512];
__device__ int   g_bbaseM[512];
__device__ __align__(256) float g_pC[(size_t)NCN * 2];
__device__ __align__(256) float g_pM[(size_t)NMN * 2];
__device__ __align__(16)  float g_qC[128];    // W1_c2t @ Wf
__device__ __align__(16)  float g_qM[128];    // W1_m2t @ Wf
__device__ __align__(16)  float g_rbC[2];
__device__ __align__(16)  float g_rbM[2];

__device__ __forceinline__ void red_add_v2(float* addr, float x, float y) {
    asm volatile("red.global.add.v2.f32 [%0], {%1, %2};"
                 :: "l"(addr), "f"(x), "f"(y) : "memory");
}

// packed fp32x2 helpers (Blackwell FFMA2 — PTX-only path)
__device__ __forceinline__ unsigned long long pack_dup_f32(float a) {
    unsigned long long r;
    asm("mov.b64 %0, {%1, %1};" : "=l"(r) : "f"(a));
    return r;
}
__device__ __forceinline__ void fma_f32x2(unsigned long long& acc,
                                          unsigned long long a, unsigned long long b) {
    asm("fma.rn.f32x2 %0, %1, %2, %0;" : "+l"(acc) : "l"(a), "l"(b));
}
__device__ __forceinline__ float2 unpack_f32x2(unsigned long long v) {
    float2 f;
    asm("mov.b64 {%0, %1}, %2;" : "=f"(f.x), "=f"(f.y) : "l"(v));
    return f;
}

// ---------------- kernels ----------------

// all four dst histograms in one launch
__global__ void count_all_kernel(const int* __restrict__ d_c2t, const int* __restrict__ d_m2t,
                                 const int* __restrict__ d_t2c, const int* __restrict__ d_t2m)
{
    int i = blockIdx.x * blockDim.x + threadIdx.x;
    if (i < EN)            atomicAdd(&g_cntT1[d_c2t[i]], 1);
    else if (i < 2 * EN)   atomicAdd(&g_cntT2[d_m2t[i - EN]], 1);
    else if (i < 3 * EN)   atomicAdd(&g_cntC[d_t2c[i - 2 * EN]], 1);
    else if (i < 4 * EN)   atomicAdd(&g_cntM[d_t2m[i - 3 * EN]], 1);
}

// inv weights for transactions + output init to bf
__global__ void inv_out_kernel(const float* __restrict__ bf, float* __restrict__ out)
{
    int i = blockIdx.x * blockDim.x + threadIdx.x;
    if (i < NTN) {
        int c1 = g_cntT1[i]; g_invT1[i] = 1.0f / (float)(c1 > 0 ? c1 : 1);
        int c2 = g_cntT2[i]; g_invT2[i] = 1.0f / (float)(c2 > 0 ? c2 : 1);
        ((float2*)out)[i] = make_float2(bf[0], bf[1]);
    }
}

// ---- CSR build (both relations in each launch) ----
__global__ void blocksum_both_kernel()
{
    __shared__ int s[256];
    bool isC = blockIdx.x < NB_C;
    int blk = isC ? blockIdx.x : blockIdx.x - NB_C;
    const int* cnt = isC ? g_cntC : g_cntM;
    int n = isC ? NCN : NMN;
    int i = blk * 256 + threadIdx.x;
    s[threadIdx.x] = (i < n) ? cnt[i] : 0;
    __syncthreads();
    #pragma unroll
    for (int o = 128; o > 0; o >>= 1) {
        if (threadIdx.x < o) s[threadIdx.x] += s[threadIdx.x + o];
        __syncthreads();
    }
    if (threadIdx.x == 0) (isC ? g_bsumC : g_bsumM)[blk] = s[0];
}

__global__ void scan_both_kernel()
{
    __shared__ int s[512];
    bool isC = blockIdx.x == 0;
    const int* bsum = isC ? g_bsumC : g_bsumM;
    int* bbase = isC ? g_bbaseC : g_bbaseM;
    int nb = isC ? NB_C : NB_M;
    int t = threadIdx.x;
    int v = (t < nb) ? bsum[t] : 0;
    s[t] = v;
    __syncthreads();
    #pragma unroll
    for (int o = 1; o < 512; o <<= 1) {
        int add = (t >= o) ? s[t - o] : 0;
        __syncthreads();
        s[t] += add;
        __syncthreads();
    }
    if (t < nb) bbase[t] = s[t] - v;   // exclusive
}

__global__ void finalize_both_kernel()
{
    __shared__ int s[256];
    bool isC = blockIdx.x < NB_C;
    int blk = isC ? blockIdx.x : blockIdx.x - NB_C;
    const int* cnt = isC ? g_cntC : g_cntM;
    const int* bbase = isC ? g_bbaseC : g_bbaseM;
    int* base = isC ? g_baseC : g_baseM;
    int* cur = isC ? g_curC : g_curM;
    int n = isC ? NCN : NMN;
    int t = threadIdx.x;
    int i = blk * 256 + t;
    int v = (i < n) ? cnt[i] : 0;
    s[t] = v;
    __syncthreads();
    #pragma unroll
    for (int o = 1; o < 256; o <<= 1) {
        int add = (t >= o) ? s[t - o] : 0;
        __syncthreads();
        s[t] += add;
        __syncthreads();
    }
    if (i < n) {
        int b = bbase[blk] + s[t] - v;
        base[i] = b;
        cur[i]  = b;
    }
}

__global__ void bucket_both_kernel(const int* __restrict__ s_t2c, const int* __restrict__ d_t2c,
                                   const int* __restrict__ s_t2m, const int* __restrict__ d_t2m)
{
    int i = blockIdx.x * blockDim.x + threadIdx.x;
    if (i < EN) {
        int d = d_t2c[i];
        int pos = atomicAdd(&g_curC[d], 1);
        g_permC[pos] = s_t2c[i];
    } else if (i < 2 * EN) {
        int e = i - EN;
        int d = d_t2m[e];
        int pos = atomicAdd(&g_curM[d], 1);
        g_permM[pos] = s_t2m[e];
    }
}

// q = W1 @ Wf (64x64 @ 64x2), rb = b1 @ Wf — tiny, one block
__global__ void precompute_q_kernel(const float* __restrict__ W1c, const float* __restrict__ b1c,
                                    const float* __restrict__ W1m, const float* __restrict__ b1m,
                                    const float* __restrict__ Wf)
{
    int tid = threadIdx.x;  // 256 threads
    if (tid < 128) {
        int k = tid >> 1, j = tid & 1;
        float s = 0.f;
        #pragma unroll
        for (int h = 0; h < 64; h++) s = fmaf(W1c[k * 64 + h], Wf[h * 2 + j], s);
        g_qC[tid] = s;
    } else {
        int t = tid - 128;
        int k = t >> 1, j = t & 1;
        float s = 0.f;
        #pragma unroll
        for (int h = 0; h < 64; h++) s = fmaf(W1m[k * 64 + h], Wf[h * 2 + j], s);
        g_qM[t] = s;
    }
    if (tid < 2) {
        float s = 0.f;
        #pragma unroll
        for (int h = 0; h < 64; h++) s = fmaf(b1c[h], Wf[h * 2 + tid], s);
        g_rbC[tid] = s;
    }
    if (tid >= 128 && tid < 130) {
        int j = tid - 128;
        float s = 0.f;
        #pragma unroll
        for (int h = 0; h < 64; h++) s = fmaf(b1m[h], Wf[h * 2 + j], s);
        g_rbM[j] = s;
    }
}

// ---- FUSED (both relations in ONE grid):
//   gather(mean feat rows per dst) -> smem A tile ->
//   h = lrelu(A @ W0 + b0*gate) -> p = h @ q + rb  (2 outputs/row)
// smem floats: sA[64*128] | sW[128*64] | sb[64] | sq[128] | sg[64] | srb[2]
#define FUSED_SMEM_FLOATS (64*128 + 128*64 + 64 + 128 + 64 + 2)
__global__ __launch_bounds__(256) void fused_both_kernel(
    const float* __restrict__ feat,
    const float* __restrict__ W0c, const float* __restrict__ b0c,
    const float* __restrict__ W0m, const float* __restrict__ b0m)
{
    extern __shared__ float smem[];
    float* sA  = smem;                 // 64 x 128
    float* sW  = sA + 64 * 128;        // 128 x 64
    float* sb  = sW + 128 * 64;
    float* sq  = sb + 64;
    float* sg  = sq + 128;
    float* srb = sg + 64;

    const bool isC = blockIdx.x < NBF_C;
    const int blk = isC ? blockIdx.x : blockIdx.x - NBF_C;
    const int M = isC ? NCN : NMN;
    const int* __restrict__ perm = isC ? g_permC : g_permM;
    const int* __restrict__ base = isC ? g_baseC : g_baseM;
    const int* __restrict__ cnt  = isC ? g_cntC  : g_cntM;
    const float* __restrict__ W0 = isC ? W0c : W0m;
    const float* __restrict__ b0 = isC ? b0c : b0m;
    const float* __restrict__ q  = isC ? g_qC : g_qM;
    const float* __restrict__ rb = isC ? g_rbC : g_rbM;
    float* __restrict__ p_out    = isC ? g_pC : g_pM;

    const int tid = threadIdx.x;
    const int row0 = blk * 64;

    // cooperative load of W0 (8192 floats) + small vectors
    #pragma unroll
    for (int l = 0; l < 32; l++) sW[l * 256 + tid] = W0[l * 256 + tid];
    if (tid < 64) sb[tid] = b0[tid];
    else if (tid < 192) sq[tid - 64] = q[tid - 64];
    else if (tid < 194) srb[tid - 192] = rb[tid - 192];

    // gather: each warp accumulates 8 dst rows directly into sA (mean-normalized)
    const int wid = tid >> 5, lane = tid & 31;
    #pragma unroll
    for (int i = 0; i < 8; i++) {
        int rl = wid * 8 + i;
        int gr = row0 + rl;
        float4 a0 = make_float4(0.f, 0.f, 0.f, 0.f);
        float4 a1 = make_float4(0.f, 0.f, 0.f, 0.f);
        float invd = 0.f, gate = 0.f;
        if (gr < M) {
            int b = base[gr];
            int c = cnt[gr];
            invd = 1.0f / (float)(c > 0 ? c : 1);
            gate = (c > 0) ? 1.0f : 0.0f;
            int e = 0;
            for (; e + 1 < c; e += 2) {
                int s0 = __ldg(&perm[b + e]);
                int s1 = __ldg(&perm[b + e + 1]);
                float4 v0 = *(const float4*)(feat + (size_t)s0 * 128 + lane * 4);
                float4 v1 = *(const float4*)(feat + (size_t)s1 * 128 + lane * 4);
                a0.x += v0.x; a0.y += v0.y; a0.z += v0.z; a0.w += v0.w;
                a1.x += v1.x; a1.y += v1.y; a1.z += v1.z; a1.w += v1.w;
            }
            if (e < c) {
                int s0 = __ldg(&perm[b + e]);
                float4 v0 = *(const float4*)(feat + (size_t)s0 * 128 + lane * 4);
                a0.x += v0.x; a0.y += v0.y; a0.z += v0.z; a0.w += v0.w;
            }
        }
        a0.x = (a0.x + a1.x) * invd;
        a0.y = (a0.y + a1.y) * invd;
        a0.z = (a0.z + a1.z) * invd;
        a0.w = (a0.w + a1.w) * invd;
        *(float4*)(sA + rl * 128 + lane * 4) = a0;
        if (lane == 0) sg[rl] = gate;
    }
    __syncthreads();

    // GEMM 64x64 tile, K=128, packed fp32x2 accumulation over column pairs
    const int tx = tid & 15;   // 4 cols each
    const int ty = tid >> 4;   // 4 rows each
    unsigned long long acc2[4][2];
    #pragma unroll
    for (int i = 0; i < 4; i++) { acc2[i][0] = 0ull; acc2[i][1] = 0ull; }

    #pragma unroll 4
    for (int kk = 0; kk < 128; kk++) {
        const unsigned long long* wrow =
            (const unsigned long long*)(sW + kk * 64 + tx * 4);
        unsigned long long bv0 = wrow[0];
        unsigned long long bv1 = wrow[1];
        #pragma unroll
        for (int i = 0; i < 4; i++) {
            float a = sA[(ty * 4 + i) * 128 + kk];
            unsigned long long av = pack_dup_f32(a);
            fma_f32x2(acc2[i][0], av, bv0);
            fma_f32x2(acc2[i][1], av, bv1);
        }
    }

    // epilogue: bias-gate + lrelu + 2-d projection, reduce over the 16 tx lanes
    #pragma unroll
    for (int i = 0; i < 4; i++) {
        int rl = ty * 4 + i;
        int r = row0 + rl;
        float p0 = 0.f, p1 = 0.f;
        if (r < M) {
            float gate = sg[rl];
            float2 v01 = unpack_f32x2(acc2[i][0]);
            float2 v23 = unpack_f32x2(acc2[i][1]);
            float v[4] = { v01.x, v01.y, v23.x, v23.y };
            #pragma unroll
            for (int j = 0; j < 4; j++) {
                int col = tx * 4 + j;
                float h = v[j] + sb[col] * gate;
                h = (h > 0.f) ? h : 0.01f * h;      // leaky_relu
                p0 = fmaf(h, sq[col * 2],     p0);
                p1 = fmaf(h, sq[col * 2 + 1], p1);
            }
        }
        #pragma unroll
        for (int o = 8; o >= 1; o >>= 1) {
            p0 += __shfl_xor_sync(0xffffffffu, p0, o);
            p1 += __shfl_xor_sync(0xffffffffu, p1, o);
        }
        if (tx == 0 && r < M) {
            p_out[(size_t)r * 2]     = p0 + srb[0];
            p_out[(size_t)r * 2 + 1] = p1 + srb[1];
        }
    }
}

// layer-1 scatter: both relations, one thread per edge, 8 B payload
__global__ __launch_bounds__(256) void scatter2_kernel(
    const int* __restrict__ s_c2t, const int* __restrict__ d_c2t,
    const int* __restrict__ s_m2t, const int* __restrict__ d_m2t,
    float* __restrict__ out)
{
    int i = blockIdx.x * blockDim.x + threadIdx.x;
    if (i >= 2 * EN) return;
    int s, d;
    const float* p;
    float w;
    if (i < EN) {
        s = s_c2t[i]; d = d_c2t[i];
        p = g_pC + (size_t)s * 2;
        w = g_invT1[d];
    } else {
        int e = i - EN;
        s = s_m2t[e]; d = d_m2t[e];
        p = g_pM + (size_t)s * 2;
        w = g_invT2[d];
    }
    float2 v = *(const float2*)p;
    red_add_v2(out + (size_t)d * 2, v.x * w, v.y * w);
}

// ---------------- launch ----------------
extern "C" void kernel_launch(void* const* d_in, const int* in_sizes, int n_in,
                              void* d_out, int out_size)
{
    (void)in_sizes; (void)n_in; (void)out_size;

    const float* feat   = (const float*)d_in[0];
    const int* s_c2t    = (const int*)d_in[3];
    const int* d_c2t    = (const int*)d_in[4];
    const int* s_m2t    = (const int*)d_in[5];
    const int* d_m2t    = (const int*)d_in[6];
    const int* s_t2c    = (const int*)d_in[7];
    const int* d_t2c    = (const int*)d_in[8];
    const int* s_t2m    = (const int*)d_in[9];
    const int* d_t2m    = (const int*)d_in[10];
    const float* W1_c2t = (const float*)d_in[13];
    const float* b1_c2t = (const float*)d_in[14];
    const float* W1_m2t = (const float*)d_in[17];
    const float* b1_m2t = (const float*)d_in[18];
    const float* W0_t2c = (const float*)d_in[19];
    const float* b0_t2c = (const float*)d_in[20];
    const float* W0_t2m = (const float*)d_in[23];
    const float* b0_t2m = (const float*)d_in[24];
    const float* Wf     = (const float*)d_in[27];
    const float* bf     = (const float*)d_in[28];
    float* out = (float*)d_out;

    void *cntC_p, *cntM_p, *cntT1_p, *cntT2_p;
    cudaGetSymbolAddress(&cntC_p,  g_cntC);
    cudaGetSymbolAddress(&cntM_p,  g_cntM);
    cudaGetSymbolAddress(&cntT1_p, g_cntT1);
    cudaGetSymbolAddress(&cntT2_p, g_cntT2);

    const int fused_smem = FUSED_SMEM_FLOATS * (int)sizeof(float);
    cudaFuncSetAttribute(fused_both_kernel,
                         cudaFuncAttributeMaxDynamicSharedMemorySize, fused_smem);

    cudaMemsetAsync(cntC_p,  0, sizeof(g_cntC),  0);
    cudaMemsetAsync(cntM_p,  0, sizeof(g_cntM),  0);
    cudaMemsetAsync(cntT1_p, 0, sizeof(g_cntT1), 0);
    cudaMemsetAsync(cntT2_p, 0, sizeof(g_cntT2), 0);

    count_all_kernel<<<(4 * EN + 255) / 256, 256>>>(d_c2t, d_m2t, d_t2c, d_t2m);
    precompute_q_kernel<<<1, 256>>>(W1_c2t, b1_c2t, W1_m2t, b1_m2t, Wf);
    inv_out_kernel<<<(NTN + 255) / 256, 256>>>(bf, out);

    // CSR build (C and M in the same launches)
    blocksum_both_kernel<<<NB_C + NB_M, 256>>>();
    scan_both_kernel<<<2, 512>>>();
    finalize_both_kernel<<<NB_C + NB_M, 256>>>();
    bucket_both_kernel<<<(2 * EN + 255) / 256, 256>>>(s_t2c, d_t2c, s_t2m, d_t2m);

    // fused gather + GEMM + projection, both relations in one grid
    fused_both_kernel<<<NBF_C + NBF_M, 256, fused_smem>>>(
        feat, W0_t2c, b0_t2c, W0_t2m, b0_t2m);

    // layer-1 scatter straight into the output
    scatter2_kernel<<<(2 * EN + 255) / 256, 256>>>(s_c2t, d_c2t, s_m2t, d_m2t, out);
}